// round 8
// baseline (speedup 1.0000x reference)
#include <cuda_runtime.h>
#include <cuda_fp16.h>
#include <math.h>
#include <stdint.h>

// ---------------- problem constants ----------------
#define IN_DIM   768
#define HID      3072
#define BATCH    64
#define NCLS     6
#define NUM_PATCH 576
#define ATOMS    5
#define SEQ      (NCLS + NUM_PATCH)          // 582
#define M_PATCH  (BATCH * NUM_PATCH)         // 36864
#define M_CLS    (BATCH * NCLS)              // 384
#define M_ALL    (M_PATCH + M_CLS)           // 37248
#define M_PAD    37376                       // 146 * 256
#define MC_PAD   512                         // padded cls rows (2 tiles of 256)

// ---------------- device scratch (plain fp16 operands) ----------------
__device__ __half g_xh  [(size_t)M_PAD * IN_DIM];
__device__ __half g_w1t [(size_t)HID * IN_DIM];
__device__ __half g_hid [(size_t)M_PAD * HID];
__device__ __half g_w2t [(size_t)IN_DIM * HID];
__device__ __half g_wint [(size_t)ATOMS * HID * IN_DIM];
__device__ __half g_hm  [(size_t)ATOMS * MC_PAD * HID];
__device__ __half g_woutt[(size_t)ATOMS * IN_DIM * HID];
__device__ float g_allo[(size_t)ATOMS * ATOMS * MC_PAD * IN_DIM];
__device__ float g_e0  [(size_t)MC_PAD * IN_DIM];

__device__ __forceinline__ float gelu_f(float v) {
    return 0.5f * v * (1.0f + erff(v * 0.7071067811865476f));
}

// ---------------- PTX helpers (baseline sm_80+ only) ----------------
__device__ __forceinline__ uint32_t smem_u32(const void* p) {
    uint32_t a;
    asm("{ .reg .u64 t; cvta.to.shared.u64 t, %1; cvt.u32.u64 %0, t; }" : "=r"(a) : "l"(p));
    return a;
}
__device__ __forceinline__ void cp16(uint32_t d, const void* s) {
    asm volatile("cp.async.cg.shared.global [%0], [%1], 16;" :: "r"(d), "l"(s));
}
#define CP_COMMIT()  asm volatile("cp.async.commit_group;" ::: "memory")
#define CP_WAIT(n)   asm volatile("cp.async.wait_group %0;" :: "n"(n) : "memory")

__device__ __forceinline__ void ldsm_x4(uint32_t& r0, uint32_t& r1, uint32_t& r2, uint32_t& r3,
                                        uint32_t addr) {
    asm volatile("ldmatrix.sync.aligned.m8n8.x4.shared.b16 {%0,%1,%2,%3}, [%4];"
                 : "=r"(r0), "=r"(r1), "=r"(r2), "=r"(r3) : "r"(addr));
}
__device__ __forceinline__ void mma_f16(float& c0, float& c1, float& c2, float& c3,
                                        uint32_t a0, uint32_t a1, uint32_t a2, uint32_t a3,
                                        uint32_t b0, uint32_t b1) {
    asm volatile("mma.sync.aligned.m16n8k16.row.col.f32.f16.f16.f32 "
                 "{%0,%1,%2,%3}, {%4,%5,%6,%7}, {%8,%9}, {%0,%1,%2,%3};"
                 : "+f"(c0), "+f"(c1), "+f"(c2), "+f"(c3)
                 : "r"(a0), "r"(a1), "r"(a2), "r"(a3), "r"(b0), "r"(b1));
}
__device__ __forceinline__ uint32_t sw128(uint32_t off) {
    return off ^ ((off >> 3) & 0x70);
}

// ---------------- HMMA GEMM core ----------------
// CTA tile 256x128, BK=64, 8 warps as 4(M) x 2(N), warp tile 64x64.
// 3-stage cp.async, 1 CTA/SM (144 KB smem, ~200 regs).
#define BM 256
#define BN 128
#define BK 64
#define STAGES 3
#define A_STG (BM * 128)                    // 32 KB
#define B_STG (BN * 128)                    // 16 KB
#define STG   (A_STG + B_STG)               // 48 KB
#define SMEM_DYN (STAGES * STG)             // 147456

#define A_NBX    (HID / BN)                 // 24
#define A_MT     (M_PAD / BM)               // 146
#define A_NBIG   (A_NBX * A_MT)             // 3504
#define A_NSMALL (A_NBX * 2 * ATOMS)        // 240
#define A_TOTAL  (A_NBIG + A_NSMALL)        // 3744
#define B_NBX    (IN_DIM / BN)              // 6
#define B_NBIG   (B_NBX * A_MT)             // 876
#define B_NSMALL (B_NBX * 2 * ATOMS * ATOMS)// 300
#define B_TOTAL  (B_NBIG + B_NSMALL)        // 1176

// PHASE 0: d->h GELU, fp16 output (GEMM1 + GEMM3);  K = IN_DIM
// PHASE 1: h->d, fp32 output (GEMM2 scatter + GEMM4); K = HID
template<int PHASE>
__global__ __launch_bounds__(256, 1)
void mlp_gemm(const __half* __restrict__ xh,
              const __half* __restrict__ wBig,
              const __half* __restrict__ wSmall,
              const __half* __restrict__ hm,
              const float* __restrict__ biasBig,
              const float* __restrict__ biasSmall,
              __half* __restrict__ outBigH,
              __half* __restrict__ outSmallH,
              float* __restrict__ outBigF,
              float* __restrict__ outE0,
              float* __restrict__ outSmallF)
{
    extern __shared__ char smem[];
    const uint32_t sb = smem_u32(smem);
    const int tid  = threadIdx.x;
    const int wid  = tid >> 5, lane = tid & 31;
    const int wm   = wid >> 1;               // 0..3  (M, 64 rows each)
    const int wn   = wid & 1;                // 0..1  (N, 64 cols each)

    const int bi = blockIdx.x;
    const int K  = (PHASE == 0) ? IN_DIM : HID;
    const int C  = K >> 6;
    int bm, bn, sub;
    const __half* A;
    const __half* B;
    const float* bias;
    if (PHASE == 0) {
        if (bi < A_NBIG) {
            sub = 0;
            bm = (bi / A_NBX) * BM; bn = (bi % A_NBX) * BN;
            A = xh; B = wBig; bias = biasBig;
        } else {
            int r = bi - A_NBIG;
            int a = r / (A_NBX * 2);
            r -= a * (A_NBX * 2);
            sub = 1 + a;
            bm = (r / A_NBX) * BM; bn = (r % A_NBX) * BN;
            A = xh + (size_t)M_PATCH * IN_DIM;      // 512-row cls+pad window
            B = wSmall + (size_t)a * HID * IN_DIM;
            bias = biasSmall + (size_t)a * HID;
        }
    } else {
        if (bi < B_NBIG) {
            sub = 0;
            bm = (bi / B_NBX) * BM; bn = (bi % B_NBX) * BN;
            A = xh; B = wBig; bias = biasBig;
        } else {
            int r = bi - B_NBIG;
            int z = r / (B_NBX * 2);
            r -= z * (B_NBX * 2);
            sub = 1 + z;
            bm = (r / B_NBX) * BM; bn = (r % B_NBX) * BN;
            int a = z / ATOMS, o = z % ATOMS;
            A = hm + (size_t)a * MC_PAD * HID;
            B = wSmall + (size_t)o * IN_DIM * HID;
            bias = biasSmall + (size_t)o * IN_DIM;
        }
    }

    const __half* aG0 = A + (size_t)bm * K;
    const __half* bG0 = B + (size_t)bn * K;

    auto loadChunk = [&](int c) {
        const int slot = c % STAGES;
        const uint32_t aS = sb + (uint32_t)slot * STG;
        const uint32_t bS = aS + A_STG;
        const __half* aG = aG0 + c * BK;
        const __half* bG = bG0 + c * BK;
        #pragma unroll
        for (int t = 0; t < 8; t++) {              // A: 2048 chunks of 16B
            int i = t * 256 + tid;
            int row = i >> 3, g = i & 7;
            uint32_t off = (uint32_t)(row * 128 + g * 16);
            cp16(aS + sw128(off), aG + (size_t)row * K + g * 8);
        }
        #pragma unroll
        for (int t = 0; t < 4; t++) {              // B: 1024 chunks
            int i = t * 256 + tid;
            int row = i >> 3, g = i & 7;
            uint32_t off = (uint32_t)(row * 128 + g * 16);
            cp16(bS + sw128(off), bG + (size_t)row * K + g * 8);
        }
        CP_COMMIT();
    };

    float acc[4][8][4];
    #pragma unroll
    for (int i = 0; i < 4; i++)
        #pragma unroll
        for (int j = 0; j < 8; j++)
            #pragma unroll
            for (int q = 0; q < 4; q++) acc[i][j][q] = 0.0f;

    loadChunk(0);
    loadChunk(1);

    const int aRow = wm * 64 + (lane & 15);
    const int aCol = (lane >> 4) * 16;
    const int bRow = wn * 64 + ((lane >> 4) & 1) * 8 + (lane & 7);
    const int bCol = ((lane >> 3) & 1) * 16;

    for (int c = 0; c < C; c++) {
        if (c + 2 < C) { CP_WAIT(1); } else { CP_WAIT(0); }
        __syncthreads();
        if (c + 2 < C) loadChunk(c + 2);

        const int slot = c % STAGES;
        const uint32_t aS = sb + (uint32_t)slot * STG;
        const uint32_t bS = aS + A_STG;

        #pragma unroll
        for (int kk = 0; kk < 4; kk++) {
            uint32_t af[4][4];
            #pragma unroll
            for (int mt = 0; mt < 4; mt++) {
                uint32_t off = (uint32_t)((aRow + mt * 16) * 128 + kk * 32 + aCol);
                ldsm_x4(af[mt][0], af[mt][1], af[mt][2], af[mt][3], aS + sw128(off));
            }
            uint32_t bf[8][2];
            #pragma unroll
            for (int pr = 0; pr < 4; pr++) {
                uint32_t off = (uint32_t)((bRow + pr * 16) * 128 + kk * 32 + bCol);
                uint32_t r0, r1, r2, r3;
                ldsm_x4(r0, r1, r2, r3, bS + sw128(off));
                bf[pr * 2 + 0][0] = r0; bf[pr * 2 + 0][1] = r1;
                bf[pr * 2 + 1][0] = r2; bf[pr * 2 + 1][1] = r3;
            }
            #pragma unroll
            for (int mt = 0; mt < 4; mt++)
                #pragma unroll
                for (int nt = 0; nt < 8; nt++)
                    mma_f16(acc[mt][nt][0], acc[mt][nt][1], acc[mt][nt][2], acc[mt][nt][3],
                            af[mt][0], af[mt][1], af[mt][2], af[mt][3],
                            bf[nt][0], bf[nt][1]);
        }
    }

    // ---------------- epilogue ----------------
    const int q = lane & 3;
    #pragma unroll
    for (int mt = 0; mt < 4; mt++) {
        #pragma unroll
        for (int h = 0; h < 2; h++) {
            const int rowg = bm + wm * 64 + mt * 16 + (lane >> 2) + h * 8;
            __half* rpH = nullptr;
            float*  rpF = nullptr;
            if (PHASE == 0) {
                rpH = (sub == 0 ? outBigH : outSmallH + (size_t)(sub - 1) * MC_PAD * HID)
                      + (size_t)rowg * HID;
            } else if (sub == 0) {
                if (rowg < M_PATCH) {
                    int bb = rowg / NUM_PATCH, p = rowg - bb * NUM_PATCH;
                    rpF = outBigF + (size_t)(bb * SEQ + NCLS + p) * IN_DIM;
                } else {
                    rpF = outE0 + (size_t)(rowg - M_PATCH) * IN_DIM;
                }
            } else {
                rpF = outSmallF + (size_t)(sub - 1) * MC_PAD * IN_DIM + (size_t)rowg * IN_DIM;
            }
            #pragma unroll
            for (int nt = 0; nt < 8; nt++) {
                const int col = bn + wn * 64 + nt * 8 + q * 2;
                float v0 = acc[mt][nt][h * 2 + 0] + bias[col];
                float v1 = acc[mt][nt][h * 2 + 1] + bias[col + 1];
                if (PHASE == 0) {
                    v0 = gelu_f(v0); v1 = gelu_f(v1);
                    __half2 hh; hh.x = __float2half(v0); hh.y = __float2half(v1);
                    *reinterpret_cast<__half2*>(rpH + col) = hh;
                } else {
                    *reinterpret_cast<float2*>(rpF + col) = make_float2(v0, v1);
                }
            }
        }
    }
}

// ---------------- fused conversion kernel (single launch) ----------------
#define CX_BLK   (M_ALL * IN_DIM / 4 / 256)            // 27936
#define WT_W1    (IN_DIM / 32 * (HID / 32))            // 2304
#define WT_W2    (HID / 32 * (IN_DIM / 32))            // 2304
#define WT_WIN   (WT_W1 * ATOMS)
#define WT_WOUT  (WT_W2 * ATOMS)
#define PAD_BLK  ((M_PAD - M_ALL) * IN_DIM / 4 / 256)  // 96
#define CONV_TOTAL (CX_BLK + WT_W1 + WT_W2 + WT_WIN + WT_WOUT + PAD_BLK)

__global__ __launch_bounds__(256)
void conv_all(const float* __restrict__ x,   __half* __restrict__ xh,
              const float* __restrict__ W1,  __half* __restrict__ w1t,
              const float* __restrict__ W2,  __half* __restrict__ w2t,
              const float* __restrict__ Win, __half* __restrict__ wint,
              const float* __restrict__ Wout,__half* __restrict__ woutt)
{
    int bi = blockIdx.x;
    if (bi < CX_BLK) {
        int idx = bi * 256 + threadIdx.x;            // units of 4 elems
        int m  = idx / (IN_DIM / 4);
        int kp = (idx - m * (IN_DIM / 4)) * 4;
        int src;
        if (m < M_PATCH) { int b = m / NUM_PATCH, p = m - b * NUM_PATCH; src = b * SEQ + NCLS + p; }
        else             { int rr = m - M_PATCH; int b = rr / NCLS, t = rr - b * NCLS; src = b * SEQ + t; }
        float4 vv = *reinterpret_cast<const float4*>(x + (size_t)src * IN_DIM + kp);
        __half2 h01; h01.x = __float2half(vv.x); h01.y = __float2half(vv.y);
        __half2 h23; h23.x = __float2half(vv.z); h23.y = __float2half(vv.w);
        uint2 pk; pk.x = *reinterpret_cast<uint32_t*>(&h01); pk.y = *reinterpret_cast<uint32_t*>(&h23);
        *reinterpret_cast<uint2*>(xh + (size_t)m * IN_DIM + kp) = pk;
        return;
    }
    bi -= CX_BLK;

    if (bi >= WT_W1 + WT_W2 + WT_WIN + WT_WOUT) {
        // zero-fill xh pad rows [M_ALL, M_PAD)
        int pb = bi - (WT_W1 + WT_W2 + WT_WIN + WT_WOUT);
        int idx = pb * 256 + threadIdx.x;            // units of 4 elems
        uint2 z; z.x = 0u; z.y = 0u;
        *reinterpret_cast<uint2*>(xh + (size_t)M_ALL * IN_DIM + (size_t)idx * 4) = z;
        return;
    }

    const float* W; __half* Wt; int K, N, tileIdx;
    if (bi < WT_W1)                   { W = W1;  Wt = w1t;  K = IN_DIM; N = HID;    tileIdx = bi; }
    else if ((bi -= WT_W1)  < WT_W2)  { W = W2;  Wt = w2t;  K = HID;    N = IN_DIM; tileIdx = bi; }
    else if ((bi -= WT_W2)  < WT_WIN) {
        int z = bi / WT_W1; tileIdx = bi - z * WT_W1;
        W = Win  + (size_t)z * IN_DIM * HID; Wt = wint  + (size_t)z * HID * IN_DIM;
        K = IN_DIM; N = HID;
    } else {
        bi -= WT_WIN;
        int z = bi / WT_W2; tileIdx = bi - z * WT_W2;
        W = Wout + (size_t)z * HID * IN_DIM; Wt = woutt + (size_t)z * IN_DIM * HID;
        K = HID; N = IN_DIM;
    }

    __shared__ float t[32][33];
    const int ktiles = K / 32;
    int k0 = (tileIdx % ktiles) * 32, n0 = (tileIdx / ktiles) * 32;
    int tx = threadIdx.x & 31, ty = threadIdx.x >> 5;
    #pragma unroll
    for (int i = 0; i < 4; i++)
        t[ty + i * 8][tx] = W[(size_t)(k0 + ty + i * 8) * N + n0 + tx];
    __syncthreads();
    #pragma unroll
    for (int i = 0; i < 4; i++) {
        int n = n0 + ty + i * 8;
        Wt[(size_t)n * K + (k0 + tx)] = __float2half(t[tx][ty + i * 8]);
    }
}

// ---------------- gating + expert mixing ----------------
__global__ __launch_bounds__(256)
void gate_mix_kernel(const float* __restrict__ x,
                     const float* __restrict__ Wg,
                     const float* __restrict__ e0,
                     const float* __restrict__ allo,
                     float* __restrict__ out)
{
    const int n = blockIdx.x;
    const int b = n / NCLS;
    const int t = n - b * NCLS;
    const int a = t % ATOMS;

    __shared__ float scls[IN_DIM];
    __shared__ float slog[6];

    const float* crow = x + (size_t)(b * SEQ + t) * IN_DIM;
    for (int i = threadIdx.x; i < IN_DIM; i += 256) scls[i] = crow[i];
    __syncthreads();

    const int w = threadIdx.x >> 5, lane = threadIdx.x & 31;
    if (w < 6) {
        const float* wg = Wg + (size_t)t * IN_DIM * 6;
        float s = 0.0f;
        for (int d = lane; d < IN_DIM; d += 32)
            s = fmaf(scls[d], wg[(size_t)d * 6 + w], s);
        #pragma unroll
        for (int off = 16; off > 0; off >>= 1)
            s += __shfl_down_sync(0xffffffffu, s, off);
        if (lane == 0) slog[w] = s;
    }
    __syncthreads();

    float l[6];
    #pragma unroll
    for (int j = 0; j < 6; j++) l[j] = slog[j];
    int i0 = 0;
    #pragma unroll
    for (int j = 1; j < 6; j++) if (l[j] > l[i0]) i0 = j;
    int i1 = (i0 == 0) ? 1 : 0;
    #pragma unroll
    for (int j = 0; j < 6; j++) if (j != i0 && l[j] > l[i1]) i1 = j;
    float p1 = expf(l[i1] - l[i0]);
    float inv = 1.0f / (1.0f + p1);
    float w0 = inv, w1 = p1 * inv;

    const float* e0row = e0 + (size_t)n * IN_DIM;
    const float* r0 = (i0 == 0) ? e0row
        : allo + ((size_t)(a * ATOMS + (i0 - 1)) * MC_PAD + n) * IN_DIM;
    const float* r1 = (i1 == 0) ? e0row
        : allo + ((size_t)(a * ATOMS + (i1 - 1)) * MC_PAD + n) * IN_DIM;

    float* orow = out + (size_t)(b * SEQ + t) * IN_DIM;
    for (int c = threadIdx.x; c < IN_DIM; c += 256)
        orow[c] = w0 * r0[c] + w1 * r1[c];
}

// ---------------- launch ----------------
extern "C" void kernel_launch(void* const* d_in, const int* in_sizes, int n_in,
                              void* d_out, int out_size)
{
    const float* x     = (const float*)d_in[0];
    const float* W1    = (const float*)d_in[1];
    const float* b1    = (const float*)d_in[2];
    const float* W2    = (const float*)d_in[3];
    const float* b2    = (const float*)d_in[4];
    const float* W_in  = (const float*)d_in[5];
    const float* b_in  = (const float*)d_in[6];
    const float* W_out = (const float*)d_in[7];
    const float* b_out = (const float*)d_in[8];
    const float* Wg    = (const float*)d_in[9];
    float* out = (float*)d_out;

    static __half *xh = nullptr, *w1t, *hid, *w2t, *wint, *hm, *woutt;
    static float *allo, *e0;
    if (!xh) {
        cudaGetSymbolAddress((void**)&xh,    g_xh);
        cudaGetSymbolAddress((void**)&w1t,   g_w1t);
        cudaGetSymbolAddress((void**)&hid,   g_hid);
        cudaGetSymbolAddress((void**)&w2t,   g_w2t);
        cudaGetSymbolAddress((void**)&wint,  g_wint);
        cudaGetSymbolAddress((void**)&hm,    g_hm);
        cudaGetSymbolAddress((void**)&woutt, g_woutt);
        cudaGetSymbolAddress((void**)&allo,  g_allo);
        cudaGetSymbolAddress((void**)&e0,    g_e0);
        cudaFuncSetAttribute((const void*)mlp_gemm<0>,
                             cudaFuncAttributeMaxDynamicSharedMemorySize, SMEM_DYN);
        cudaFuncSetAttribute((const void*)mlp_gemm<1>,
                             cudaFuncAttributeMaxDynamicSharedMemorySize, SMEM_DYN);
    }

    // launch 1: all conversions + pad zeroing fused
    conv_all<<<CONV_TOTAL, 256>>>(x, xh, W1, w1t, W2, w2t, W_in, wint, W_out, woutt);

    // launch 2: phase A (GEMM1 + GEMM3)
    mlp_gemm<0><<<A_TOTAL, 256, SMEM_DYN>>>(
        xh, w1t, wint, nullptr, b1, b_in,
        hid, hm, nullptr, nullptr, nullptr);

    // launch 3: phase B (GEMM2 + GEMM4)
    mlp_gemm<1><<<B_TOTAL, 256, SMEM_DYN>>>(
        hid, w2t, woutt, hm, b2, b_out,
        nullptr, nullptr, out, e0, allo);

    // launch 4: gating + mixing
    gate_mix_kernel<<<M_CLS, 256>>>(x, Wg, e0, allo, out);
}

// round 9
// speedup vs baseline: 1.1464x; 1.1464x over previous
#include <cuda_runtime.h>
#include <cuda_fp16.h>
#include <math.h>
#include <stdint.h>

// ---------------- problem constants ----------------
#define IN_DIM   768
#define HID      3072
#define BATCH    64
#define NCLS     6
#define NUM_PATCH 576
#define ATOMS    5
#define SEQ      (NCLS + NUM_PATCH)          // 582
#define M_PATCH  (BATCH * NUM_PATCH)         // 36864
#define M_CLS    (BATCH * NCLS)              // 384
#define M_ALL    (M_PATCH + M_CLS)           // 37248

// ---------------- device scratch (plain fp16 operands) ----------------
__device__ __half g_xh  [(size_t)M_ALL * IN_DIM];
__device__ __half g_w1t [(size_t)HID * IN_DIM];
__device__ __half g_hid [(size_t)M_ALL * HID];
__device__ __half g_w2t [(size_t)IN_DIM * HID];
__device__ __half g_wint [(size_t)ATOMS * HID * IN_DIM];
__device__ __half g_hm  [(size_t)ATOMS * M_CLS * HID];
__device__ __half g_woutt[(size_t)ATOMS * IN_DIM * HID];
__device__ float g_allo[(size_t)ATOMS * ATOMS * M_CLS * IN_DIM];
__device__ float g_e0  [(size_t)M_CLS * IN_DIM];

__device__ __forceinline__ float gelu_f(float v) {
    return 0.5f * v * (1.0f + erff(v * 0.7071067811865476f));
}

// ---------------- PTX helpers (baseline sm_80+ only) ----------------
__device__ __forceinline__ uint32_t smem_u32(const void* p) {
    uint32_t a;
    asm("{ .reg .u64 t; cvta.to.shared.u64 t, %1; cvt.u32.u64 %0, t; }" : "=r"(a) : "l"(p));
    return a;
}
__device__ __forceinline__ void cp16(uint32_t d, const void* s) {
    asm volatile("cp.async.cg.shared.global [%0], [%1], 16;" :: "r"(d), "l"(s));
}
#define CP_COMMIT()  asm volatile("cp.async.commit_group;" ::: "memory")
#define CP_WAIT(n)   asm volatile("cp.async.wait_group %0;" :: "n"(n) : "memory")

__device__ __forceinline__ void ldsm_x4(uint32_t& r0, uint32_t& r1, uint32_t& r2, uint32_t& r3,
                                        uint32_t addr) {
    asm volatile("ldmatrix.sync.aligned.m8n8.x4.shared.b16 {%0,%1,%2,%3}, [%4];"
                 : "=r"(r0), "=r"(r1), "=r"(r2), "=r"(r3) : "r"(addr));
}
__device__ __forceinline__ void mma_f16(float& c0, float& c1, float& c2, float& c3,
                                        uint32_t a0, uint32_t a1, uint32_t a2, uint32_t a3,
                                        uint32_t b0, uint32_t b1) {
    asm volatile("mma.sync.aligned.m16n8k16.row.col.f32.f16.f16.f32 "
                 "{%0,%1,%2,%3}, {%4,%5,%6,%7}, {%8,%9}, {%0,%1,%2,%3};"
                 : "+f"(c0), "+f"(c1), "+f"(c2), "+f"(c3)
                 : "r"(a0), "r"(a1), "r"(a2), "r"(a3), "r"(b0), "r"(b1));
}
__device__ __forceinline__ uint32_t sw128(uint32_t off) {
    return off ^ ((off >> 3) & 0x70);
}

// ---------------- HMMA GEMM core ----------------
// CTA tile 128x128, BK=64, 4 warps as 2(M) x 2(N), warp tile 64x64.
// 3-stage cp.async, 128 threads, 2 CTAs/SM (96 KB smem each).
#define BM 128
#define BN 128
#define BK 64
#define STAGES 3
#define STG_BYTES (BM * 128)                     // 16 KB per operand per stage
#define SMEM_DYN (STAGES * 2 * STG_BYTES)        // 96 KB
#define NTHREADS 128

#define A_NBX    (HID / BN)                      // 24
#define A_NBIG   (A_NBX * (M_ALL / BM))          // 6984
#define A_NSMALL (A_NBX * (M_CLS / BM) * ATOMS)  // 360
#define A_TOTAL  (A_NBIG + A_NSMALL)
#define B_NBX    (IN_DIM / BN)                   // 6
#define B_NBIG   (B_NBX * (M_ALL / BM))          // 1746
#define B_NSMALL (B_NBX * (M_CLS / BM) * ATOMS * ATOMS)  // 450
#define B_TOTAL  (B_NBIG + B_NSMALL)

// PHASE 0: d->h GELU, fp16 output (GEMM1 + GEMM3);  K = IN_DIM
// PHASE 1: h->d, fp32 output (GEMM2 scatter + GEMM4); K = HID
template<int PHASE>
__global__ __launch_bounds__(NTHREADS, 2)
void mlp_gemm(const __half* __restrict__ xh,
              const __half* __restrict__ wBig,
              const __half* __restrict__ wSmall,
              const __half* __restrict__ hm,
              const float* __restrict__ biasBig,
              const float* __restrict__ biasSmall,
              __half* __restrict__ outBigH,
              __half* __restrict__ outSmallH,
              float* __restrict__ outBigF,
              float* __restrict__ outE0,
              float* __restrict__ outSmallF)
{
    extern __shared__ char smem[];
    const uint32_t sb = smem_u32(smem);
    const int tid  = threadIdx.x;
    const int wid  = tid >> 5, lane = tid & 31;
    const int wm   = wid >> 1;               // 0..1  (M, 64 rows each)
    const int wn   = wid & 1;                // 0..1  (N, 64 cols each)

    const int bi = blockIdx.x;
    const int K  = (PHASE == 0) ? IN_DIM : HID;
    const int C  = K >> 6;
    int bm, bn, sub;
    const __half* A;
    const __half* B;
    const float* bias;
    if (PHASE == 0) {
        if (bi < A_NBIG) {
            sub = 0;
            bm = (bi / A_NBX) * BM; bn = (bi % A_NBX) * BN;
            A = xh; B = wBig; bias = biasBig;
        } else {
            int r = bi - A_NBIG;
            int a = r / (A_NBX * (M_CLS / BM));
            r -= a * (A_NBX * (M_CLS / BM));
            sub = 1 + a;
            bm = (r / A_NBX) * BM; bn = (r % A_NBX) * BN;
            A = xh + (size_t)M_PATCH * IN_DIM;
            B = wSmall + (size_t)a * HID * IN_DIM;
            bias = biasSmall + (size_t)a * HID;
        }
    } else {
        if (bi < B_NBIG) {
            sub = 0;
            bm = (bi / B_NBX) * BM; bn = (bi % B_NBX) * BN;
            A = xh; B = wBig; bias = biasBig;
        } else {
            int r = bi - B_NBIG;
            int z = r / (B_NBX * (M_CLS / BM));
            r -= z * (B_NBX * (M_CLS / BM));
            sub = 1 + z;
            bm = (r / B_NBX) * BM; bn = (r % B_NBX) * BN;
            int a = z / ATOMS, o = z % ATOMS;
            A = hm + (size_t)a * M_CLS * HID;
            B = wSmall + (size_t)o * IN_DIM * HID;
            bias = biasSmall + (size_t)o * IN_DIM;
        }
    }

    const __half* aG0 = A + (size_t)bm * K;
    const __half* bG0 = B + (size_t)bn * K;

    auto loadChunk = [&](int c) {
        const int slot = c % STAGES;
        const uint32_t aS = sb + (uint32_t)slot * (2 * STG_BYTES);
        const uint32_t bS = aS + STG_BYTES;
        const __half* aG = aG0 + c * BK;
        const __half* bG = bG0 + c * BK;
        #pragma unroll
        for (int t = 0; t < 8; t++) {            // A: 1024 chunks of 16B
            int i = t * NTHREADS + tid;
            int row = i >> 3, g = i & 7;
            uint32_t off = (uint32_t)(row * 128 + g * 16);
            cp16(aS + sw128(off), aG + (size_t)row * K + g * 8);
        }
        #pragma unroll
        for (int t = 0; t < 8; t++) {            // B: 1024 chunks
            int i = t * NTHREADS + tid;
            int row = i >> 3, g = i & 7;
            uint32_t off = (uint32_t)(row * 128 + g * 16);
            cp16(bS + sw128(off), bG + (size_t)row * K + g * 8);
        }
        CP_COMMIT();
    };

    float acc[4][8][4];
    #pragma unroll
    for (int i = 0; i < 4; i++)
        #pragma unroll
        for (int j = 0; j < 8; j++)
            #pragma unroll
            for (int q = 0; q < 4; q++) acc[i][j][q] = 0.0f;

    loadChunk(0);
    loadChunk(1);

    const int aRow = wm * 64 + (lane & 15);
    const int aCol = (lane >> 4) * 16;
    const int bRow = wn * 64 + ((lane >> 4) & 1) * 8 + (lane & 7);
    const int bCol = ((lane >> 3) & 1) * 16;

    for (int c = 0; c < C; c++) {
        if (c + 2 < C) { CP_WAIT(1); } else { CP_WAIT(0); }
        __syncthreads();
        if (c + 2 < C) loadChunk(c + 2);

        const int slot = c % STAGES;
        const uint32_t aS = sb + (uint32_t)slot * (2 * STG_BYTES);
        const uint32_t bS = aS + STG_BYTES;

        #pragma unroll
        for (int kk = 0; kk < 4; kk++) {
            uint32_t af[4][4];
            #pragma unroll
            for (int mt = 0; mt < 4; mt++) {
                uint32_t off = (uint32_t)((aRow + mt * 16) * 128 + kk * 32 + aCol);
                ldsm_x4(af[mt][0], af[mt][1], af[mt][2], af[mt][3], aS + sw128(off));
            }
            uint32_t bf[8][2];
            #pragma unroll
            for (int pr = 0; pr < 4; pr++) {
                uint32_t off = (uint32_t)((bRow + pr * 16) * 128 + kk * 32 + bCol);
                uint32_t r0, r1, r2, r3;
                ldsm_x4(r0, r1, r2, r3, bS + sw128(off));
                bf[pr * 2 + 0][0] = r0; bf[pr * 2 + 0][1] = r1;
                bf[pr * 2 + 1][0] = r2; bf[pr * 2 + 1][1] = r3;
            }
            #pragma unroll
            for (int mt = 0; mt < 4; mt++)
                #pragma unroll
                for (int nt = 0; nt < 8; nt++)
                    mma_f16(acc[mt][nt][0], acc[mt][nt][1], acc[mt][nt][2], acc[mt][nt][3],
                            af[mt][0], af[mt][1], af[mt][2], af[mt][3],
                            bf[nt][0], bf[nt][1]);
        }
    }

    // ---------------- epilogue ----------------
    const int q = lane & 3;
    #pragma unroll
    for (int mt = 0; mt < 4; mt++) {
        #pragma unroll
        for (int h = 0; h < 2; h++) {
            const int rowg = bm + wm * 64 + mt * 16 + (lane >> 2) + h * 8;
            __half* rpH = nullptr;
            float*  rpF = nullptr;
            if (PHASE == 0) {
                rpH = (sub == 0 ? outBigH : outSmallH + (size_t)(sub - 1) * M_CLS * HID)
                      + (size_t)rowg * HID;
            } else if (sub == 0) {
                if (rowg < M_PATCH) {
                    int bb = rowg / NUM_PATCH, p = rowg - bb * NUM_PATCH;
                    rpF = outBigF + (size_t)(bb * SEQ + NCLS + p) * IN_DIM;
                } else {
                    rpF = outE0 + (size_t)(rowg - M_PATCH) * IN_DIM;
                }
            } else {
                rpF = outSmallF + (size_t)(sub - 1) * M_CLS * IN_DIM + (size_t)rowg * IN_DIM;
            }
            #pragma unroll
            for (int nt = 0; nt < 8; nt++) {
                const int col = bn + wn * 64 + nt * 8 + q * 2;
                float v0 = acc[mt][nt][h * 2 + 0] + bias[col];
                float v1 = acc[mt][nt][h * 2 + 1] + bias[col + 1];
                if (PHASE == 0) {
                    v0 = gelu_f(v0); v1 = gelu_f(v1);
                    __half2 hh; hh.x = __float2half(v0); hh.y = __float2half(v1);
                    *reinterpret_cast<__half2*>(rpH + col) = hh;
                } else {
                    *reinterpret_cast<float2*>(rpF + col) = make_float2(v0, v1);
                }
            }
        }
    }
}

// ---------------- fused conversion kernel (single launch) ----------------
#define CX_BLK   (M_ALL * IN_DIM / 4 / 256)            // 27936
#define WT_W1    (IN_DIM / 32 * (HID / 32))            // 2304
#define WT_W2    (HID / 32 * (IN_DIM / 32))            // 2304
#define WT_WIN   (WT_W1 * ATOMS)
#define WT_WOUT  (WT_W2 * ATOMS)
#define CONV_TOTAL (CX_BLK + WT_W1 + WT_W2 + WT_WIN + WT_WOUT)

__global__ __launch_bounds__(256)
void conv_all(const float* __restrict__ x,   __half* __restrict__ xh,
              const float* __restrict__ W1,  __half* __restrict__ w1t,
              const float* __restrict__ W2,  __half* __restrict__ w2t,
              const float* __restrict__ Win, __half* __restrict__ wint,
              const float* __restrict__ Wout,__half* __restrict__ woutt)
{
    int bi = blockIdx.x;
    if (bi < CX_BLK) {
        int idx = bi * 256 + threadIdx.x;            // units of 4 elems
        int m  = idx / (IN_DIM / 4);
        int kp = (idx - m * (IN_DIM / 4)) * 4;
        int src;
        if (m < M_PATCH) { int b = m / NUM_PATCH, p = m - b * NUM_PATCH; src = b * SEQ + NCLS + p; }
        else             { int rr = m - M_PATCH; int b = rr / NCLS, t = rr - b * NCLS; src = b * SEQ + t; }
        float4 vv = *reinterpret_cast<const float4*>(x + (size_t)src * IN_DIM + kp);
        __half2 h01; h01.x = __float2half(vv.x); h01.y = __float2half(vv.y);
        __half2 h23; h23.x = __float2half(vv.z); h23.y = __float2half(vv.w);
        uint2 pk; pk.x = *reinterpret_cast<uint32_t*>(&h01); pk.y = *reinterpret_cast<uint32_t*>(&h23);
        *reinterpret_cast<uint2*>(xh + (size_t)m * IN_DIM + kp) = pk;
        return;
    }
    bi -= CX_BLK;

    const float* W; __half* Wt; int K, N, tileIdx;
    if (bi < WT_W1)                   { W = W1;  Wt = w1t;  K = IN_DIM; N = HID;    tileIdx = bi; }
    else if ((bi -= WT_W1)  < WT_W2)  { W = W2;  Wt = w2t;  K = HID;    N = IN_DIM; tileIdx = bi; }
    else if ((bi -= WT_W2)  < WT_WIN) {
        int z = bi / WT_W1; tileIdx = bi - z * WT_W1;
        W = Win  + (size_t)z * IN_DIM * HID; Wt = wint  + (size_t)z * HID * IN_DIM;
        K = IN_DIM; N = HID;
    } else {
        bi -= WT_WIN;
        int z = bi / WT_W2; tileIdx = bi - z * WT_W2;
        W = Wout + (size_t)z * HID * IN_DIM; Wt = woutt + (size_t)z * IN_DIM * HID;
        K = HID; N = IN_DIM;
    }

    __shared__ float t[32][33];
    const int ktiles = K / 32;
    int k0 = (tileIdx % ktiles) * 32, n0 = (tileIdx / ktiles) * 32;
    int tx = threadIdx.x & 31, ty = threadIdx.x >> 5;
    #pragma unroll
    for (int i = 0; i < 4; i++)
        t[ty + i * 8][tx] = W[(size_t)(k0 + ty + i * 8) * N + n0 + tx];
    __syncthreads();
    #pragma unroll
    for (int i = 0; i < 4; i++) {
        int n = n0 + ty + i * 8;
        Wt[(size_t)n * K + (k0 + tx)] = __float2half(t[tx][ty + i * 8]);
    }
}

// ---------------- gating + expert mixing ----------------
__global__ __launch_bounds__(256)
void gate_mix_kernel(const float* __restrict__ x,
                     const float* __restrict__ Wg,
                     const float* __restrict__ e0,
                     const float* __restrict__ allo,
                     float* __restrict__ out)
{
    const int n = blockIdx.x;
    const int b = n / NCLS;
    const int t = n - b * NCLS;
    const int a = t % ATOMS;

    __shared__ float scls[IN_DIM];
    __shared__ float slog[6];

    const float* crow = x + (size_t)(b * SEQ + t) * IN_DIM;
    for (int i = threadIdx.x; i < IN_DIM; i += 256) scls[i] = crow[i];
    __syncthreads();

    const int w = threadIdx.x >> 5, lane = threadIdx.x & 31;
    if (w < 6) {
        const float* wg = Wg + (size_t)t * IN_DIM * 6;
        float s = 0.0f;
        for (int d = lane; d < IN_DIM; d += 32)
            s = fmaf(scls[d], wg[(size_t)d * 6 + w], s);
        #pragma unroll
        for (int off = 16; off > 0; off >>= 1)
            s += __shfl_down_sync(0xffffffffu, s, off);
        if (lane == 0) slog[w] = s;
    }
    __syncthreads();

    float l[6];
    #pragma unroll
    for (int j = 0; j < 6; j++) l[j] = slog[j];
    int i0 = 0;
    #pragma unroll
    for (int j = 1; j < 6; j++) if (l[j] > l[i0]) i0 = j;
    int i1 = (i0 == 0) ? 1 : 0;
    #pragma unroll
    for (int j = 0; j < 6; j++) if (j != i0 && l[j] > l[i1]) i1 = j;
    float p1 = expf(l[i1] - l[i0]);
    float inv = 1.0f / (1.0f + p1);
    float w0 = inv, w1 = p1 * inv;

    const float* e0row = e0 + (size_t)n * IN_DIM;
    const float* r0 = (i0 == 0) ? e0row
        : allo + ((size_t)(a * ATOMS + (i0 - 1)) * M_CLS + n) * IN_DIM;
    const float* r1 = (i1 == 0) ? e0row
        : allo + ((size_t)(a * ATOMS + (i1 - 1)) * M_CLS + n) * IN_DIM;

    float* orow = out + (size_t)(b * SEQ + t) * IN_DIM;
    for (int c = threadIdx.x; c < IN_DIM; c += 256)
        orow[c] = w0 * r0[c] + w1 * r1[c];
}

// ---------------- launch ----------------
extern "C" void kernel_launch(void* const* d_in, const int* in_sizes, int n_in,
                              void* d_out, int out_size)
{
    const float* x     = (const float*)d_in[0];
    const float* W1    = (const float*)d_in[1];
    const float* b1    = (const float*)d_in[2];
    const float* W2    = (const float*)d_in[3];
    const float* b2    = (const float*)d_in[4];
    const float* W_in  = (const float*)d_in[5];
    const float* b_in  = (const float*)d_in[6];
    const float* W_out = (const float*)d_in[7];
    const float* b_out = (const float*)d_in[8];
    const float* Wg    = (const float*)d_in[9];
    float* out = (float*)d_out;

    static __half *xh = nullptr, *w1t, *hid, *w2t, *wint, *hm, *woutt;
    static float *allo, *e0;
    if (!xh) {
        cudaGetSymbolAddress((void**)&xh,    g_xh);
        cudaGetSymbolAddress((void**)&w1t,   g_w1t);
        cudaGetSymbolAddress((void**)&hid,   g_hid);
        cudaGetSymbolAddress((void**)&w2t,   g_w2t);
        cudaGetSymbolAddress((void**)&wint,  g_wint);
        cudaGetSymbolAddress((void**)&hm,    g_hm);
        cudaGetSymbolAddress((void**)&woutt, g_woutt);
        cudaGetSymbolAddress((void**)&allo,  g_allo);
        cudaGetSymbolAddress((void**)&e0,    g_e0);
        cudaFuncSetAttribute((const void*)mlp_gemm<0>,
                             cudaFuncAttributeMaxDynamicSharedMemorySize, SMEM_DYN);
        cudaFuncSetAttribute((const void*)mlp_gemm<1>,
                             cudaFuncAttributeMaxDynamicSharedMemorySize, SMEM_DYN);
    }

    // launch 1: all conversions fused
    conv_all<<<CONV_TOTAL, 256>>>(x, xh, W1, w1t, W2, w2t, W_in, wint, W_out, woutt);

    // launch 2: phase A (GEMM1 + GEMM3)
    mlp_gemm<0><<<A_TOTAL, NTHREADS, SMEM_DYN>>>(
        xh, w1t, wint, nullptr, b1, b_in,
        hid, hm, nullptr, nullptr, nullptr);

    // launch 3: phase B (GEMM2 + GEMM4)
    mlp_gemm<1><<<B_TOTAL, NTHREADS, SMEM_DYN>>>(
        hid, w2t, woutt, hm, b2, b_out,
        nullptr, nullptr, out, e0, allo);

    // launch 4: gating + mixing
    gate_mix_kernel<<<M_CLS, 256>>>(x, Wg, e0, allo, out);
}